// round 3
// baseline (speedup 1.0000x reference)
#include <cuda_runtime.h>
#include <cuda_bf16.h>
#include <math.h>

#define N_FFT 16000
#define BATCH 512
#define IN_DIM 2048

// ---------------- scratch (static __device__, no allocation) ----------------
__device__ int    g_h[2 * IN_DIM];
__device__ float  g_s[2 * IN_DIM];
__device__ float2 g_tw[N_FFT];                       // W_N^j = exp(-2*pi*i*j/N)
__device__ float2 g_F1[(size_t)BATCH * N_FFT];       // scrambled spectrum of p1
__device__ float  g_norm[N_FFT];                     // per-column sum of squares

// ---------------- complex helpers ----------------
__device__ __forceinline__ float2 cmul(float2 a, float2 b) {
    return make_float2(a.x * b.x - a.y * b.y, a.x * b.y + a.y * b.x);
}
__device__ __forceinline__ float2 cmulc(float2 a, float2 b) {  // a * conj(b)
    return make_float2(a.x * b.x + a.y * b.y, a.y * b.x - a.x * b.y);
}
__device__ __forceinline__ float2 cadd(float2 a, float2 b) {
    return make_float2(a.x + b.x, a.y + b.y);
}
__device__ __forceinline__ float2 csub(float2 a, float2 b) {
    return make_float2(a.x - b.x, a.y - b.y);
}

// W5^j = exp(-2*pi*i*j/5)
__constant__ float2 W5c[5] = {
    { 1.0f,                    0.0f                   },
    { 0.30901699437494742f,   -0.95105651629515357f   },
    {-0.80901699437494742f,   -0.58778525229247314f   },
    {-0.80901699437494745f,    0.58778525229247312f   },
    { 0.30901699437494740f,    0.95105651629515364f   }
};

// Stage plan (DIF forward order): radix 2 x7 then radix 5 x3
// Ns:     16000 8000 4000 2000 1000 500 250 125 25 5
// stride: 1     2    4    8    16   32  64  128 640 3200
#define NSTAGES 10

__device__ __forceinline__ void fft_fwd_dif(float2* sm) {
    const int RAD[NSTAGES] = {2,2,2,2,2,2,2,5,5,5};
    const int NS [NSTAGES] = {16000,8000,4000,2000,1000,500,250,125,25,5};
#pragma unroll
    for (int s = 0; s < NSTAGES; s++) {
        const int r = RAD[s], Ns = NS[s];
        const int h = Ns / r, stride = N_FFT / Ns;
        if (r == 2) {
            for (int u = threadIdx.x; u < N_FFT / 2; u += blockDim.x) {
                int blk = u / h, t = u - blk * h;
                int i = blk * Ns + t;
                float2 a = sm[i], b = sm[i + h];
                float2 tw = g_tw[t * stride];
                sm[i]     = cadd(a, b);
                sm[i + h] = cmul(csub(a, b), tw);
            }
        } else {
            for (int u = threadIdx.x; u < N_FFT / 5; u += blockDim.x) {
                int blk = u / h, t = u - blk * h;
                int base = blk * Ns + t;
                float2 x[5];
#pragma unroll
                for (int q = 0; q < 5; q++) x[q] = sm[base + q * h];
#pragma unroll
                for (int p = 0; p < 5; p++) {
                    float2 acc = x[0];
#pragma unroll
                    for (int q = 1; q < 5; q++)
                        acc = cadd(acc, cmul(x[q], W5c[(p * q) % 5]));
                    if (p > 0) acc = cmul(acc, g_tw[p * t * stride]);
                    sm[base + p * h] = acc;
                }
            }
        }
        __syncthreads();
    }
}

// Exact mirror (transpose) of fft_fwd_dif with conjugate twiddles; stages in
// reverse order. Consumes the forward's scrambled output, produces natural
// order, with an overall factor of N (the unnormalized inverse we want).
__device__ __forceinline__ void fft_inv_dit(float2* sm) {
    const int RAD[NSTAGES] = {2,2,2,2,2,2,2,5,5,5};
    const int NS [NSTAGES] = {16000,8000,4000,2000,1000,500,250,125,25,5};
#pragma unroll
    for (int s = NSTAGES - 1; s >= 0; s--) {
        const int r = RAD[s], Ns = NS[s];
        const int h = Ns / r, stride = N_FFT / Ns;
        if (r == 2) {
            for (int u = threadIdx.x; u < N_FFT / 2; u += blockDim.x) {
                int blk = u / h, t = u - blk * h;
                int i = blk * Ns + t;
                float2 a = sm[i];
                float2 b = cmulc(sm[i + h], g_tw[t * stride]);  // y1 * conj(tw)
                sm[i]     = cadd(a, b);
                sm[i + h] = csub(a, b);
            }
        } else {
            for (int u = threadIdx.x; u < N_FFT / 5; u += blockDim.x) {
                int blk = u / h, t = u - blk * h;
                int base = blk * Ns + t;
                float2 y[5];
                y[0] = sm[base];
#pragma unroll
                for (int p = 1; p < 5; p++)
                    y[p] = cmulc(sm[base + p * h], g_tw[p * t * stride]);
#pragma unroll
                for (int q = 0; q < 5; q++) {
                    float2 acc = y[0];
#pragma unroll
                    for (int p = 1; p < 5; p++)
                        acc = cadd(acc, cmulc(y[p], W5c[(p * q) % 5]));
                    sm[base + q * h] = acc;
                }
            }
        }
        __syncthreads();
    }
}

// Build p (count-sketch projection) for batch row b directly in shared memory.
__device__ __forceinline__ void build_p(float2* sm, const float* x_row, int sk_off) {
    float4* sm4 = (float4*)sm;
    for (int i = threadIdx.x; i < N_FFT / 2; i += blockDim.x)
        sm4[i] = make_float4(0.f, 0.f, 0.f, 0.f);
    __syncthreads();
    for (int k = threadIdx.x; k < IN_DIM; k += blockDim.x) {
        int   hh = g_h[sk_off + k];
        float ss = g_s[sk_off + k];
        atomicAdd(&sm[hh].x, ss * x_row[k]);
    }
    __syncthreads();
}

// ---------------- kernels ----------------

__global__ void k_twiddles() {
    int j = blockIdx.x * blockDim.x + threadIdx.x;
    if (j < N_FFT) {
        double a = -2.0 * 3.14159265358979323846 * (double)j / (double)N_FFT;
        double sn, cs;
        sincos(a, &sn, &cs);
        g_tw[j] = make_float2((float)cs, (float)sn);
    }
}

// One block per sketch row: find the single +-1 nonzero; early-exit per chunk.
__global__ void k_extract(const float* __restrict__ sk1,
                          const float* __restrict__ sk2) {
    int r = blockIdx.x;
    const float* row = (r < IN_DIM) ? (sk1 + (size_t)r * N_FFT)
                                    : (sk2 + (size_t)(r - IN_DIM) * N_FFT);
    const float4* row4 = (const float4*)row;
    __shared__ int found;
    if (threadIdx.x == 0) found = 0;
    __syncthreads();
    for (int base = 0; base < N_FFT / 4; base += blockDim.x) {
        int j = base + threadIdx.x;
        if (j < N_FFT / 4) {
            float4 v = row4[j];
            if (v.x != 0.f || v.y != 0.f || v.z != 0.f || v.w != 0.f) {
                int   c   = (v.x != 0.f) ? 0 : (v.y != 0.f) ? 1 : (v.z != 0.f) ? 2 : 3;
                float val = (c == 0) ? v.x : (c == 1) ? v.y : (c == 2) ? v.z : v.w;
                g_h[r] = 4 * j + c;
                g_s[r] = val;
                found = 1;
            }
        }
        __syncthreads();
        if (found) break;
    }
}

// Forward FFT of p1 rows -> scrambled spectrum in g_F1.
__global__ void k_fftA(const float* __restrict__ x1) {
    extern __shared__ float2 sm[];
    int b = blockIdx.x;
    build_p(sm, x1 + (size_t)b * IN_DIM, 0);
    fft_fwd_dif(sm);
    float2* dst = g_F1 + (size_t)b * N_FFT;
    for (int j = threadIdx.x; j < N_FFT; j += blockDim.x) dst[j] = sm[j];
}

// Forward FFT of p2, multiply by F1 (same scrambled order), mirrored inverse,
// signed sqrt, write ss into d_out.
__global__ void k_fftB(const float* __restrict__ x2, float* __restrict__ out) {
    extern __shared__ float2 sm[];
    int b = blockIdx.x;
    build_p(sm, x2 + (size_t)b * IN_DIM, IN_DIM);
    fft_fwd_dif(sm);
    const float2* f1 = g_F1 + (size_t)b * N_FFT;
    for (int j = threadIdx.x; j < N_FFT; j += blockDim.x)
        sm[j] = cmul(sm[j], f1[j]);
    __syncthreads();
    fft_inv_dit(sm);
    float* dst = out + (size_t)b * N_FFT;
    for (int j = threadIdx.x; j < N_FFT; j += blockDim.x) {
        float c = sm[j].x;                       // factor N already included
        dst[j] = copysignf(sqrtf(fabsf(c)), c);  // signed sqrt
    }
}

__global__ void k_colnorm(const float* __restrict__ ss) {
    int d = blockIdx.x * blockDim.x + threadIdx.x;
    if (d < N_FFT) {
        float acc = 0.f;
#pragma unroll 8
        for (int b = 0; b < BATCH; b++) {
            float v = ss[(size_t)b * N_FFT + d];
            acc += v * v;
        }
        g_norm[d] = acc;
    }
}

__global__ void k_normalize(float* __restrict__ out) {
    int i = blockIdx.x * blockDim.x + threadIdx.x;
    if (i < BATCH * N_FFT) {
        int d = i % N_FFT;
        float n = sqrtf(g_norm[d]);
        out[i] = out[i] / fmaxf(n, 1e-12f);
    }
}

// ---------------- launch ----------------
extern "C" void kernel_launch(void* const* d_in, const int* in_sizes, int n_in,
                              void* d_out, int out_size) {
    const float* x1  = (const float*)d_in[0];
    const float* x2  = (const float*)d_in[1];
    const float* sk1 = (const float*)d_in[2];
    const float* sk2 = (const float*)d_in[3];
    float* out = (float*)d_out;

    const int smem = N_FFT * sizeof(float2);  // 128000 B
    cudaFuncSetAttribute(k_fftA, cudaFuncAttributeMaxDynamicSharedMemorySize, smem);
    cudaFuncSetAttribute(k_fftB, cudaFuncAttributeMaxDynamicSharedMemorySize, smem);

    k_twiddles<<<(N_FFT + 255) / 256, 256>>>();
    k_extract<<<2 * IN_DIM, 256>>>(sk1, sk2);
    k_fftA<<<BATCH, 1024, smem>>>(x1);
    k_fftB<<<BATCH, 1024, smem>>>(x2, out);
    k_colnorm<<<(N_FFT + 255) / 256, 256>>>(out);
    k_normalize<<<(BATCH * N_FFT + 255) / 256, 256>>>(out);
}

// round 4
// speedup vs baseline: 1.9667x; 1.9667x over previous
#include <cuda_runtime.h>
#include <cuda_bf16.h>
#include <math.h>

#define N_FFT 16000
#define BATCH 512
#define IN_DIM 2048
#define NTH 512

// ---------------- scratch (static __device__, no allocation) ----------------
__device__ int    g_h[2 * IN_DIM];
__device__ float  g_s[2 * IN_DIM];
__device__ float2 g_tw[N_FFT];      // W_N^j = exp(-2*pi*i*j/N)
__device__ int    g_sig[N_FFT];     // scrambled position -> natural frequency
__device__ int    g_isig[N_FFT];    // natural frequency -> scrambled position
__device__ float  g_norm[N_FFT];    // per-column sum of squares

// ---------------- complex helpers ----------------
__device__ __forceinline__ float2 cmul(float2 a, float2 b) {
    return make_float2(a.x * b.x - a.y * b.y, a.x * b.y + a.y * b.x);
}
__device__ __forceinline__ float2 cmulc(float2 a, float2 b) {  // a * conj(b)
    return make_float2(a.x * b.x + a.y * b.y, a.y * b.x - a.x * b.y);
}
__device__ __forceinline__ float2 cadd(float2 a, float2 b) {
    return make_float2(a.x + b.x, a.y + b.y);
}
__device__ __forceinline__ float2 csub(float2 a, float2 b) {
    return make_float2(a.x - b.x, a.y - b.y);
}
__device__ __forceinline__ float2 mul_negi(float2 a) {  // a * (-i)
    return make_float2(a.y, -a.x);
}
__device__ __forceinline__ float2 mul_posi(float2 a) {  // a * (+i)
    return make_float2(-a.y, a.x);
}

// W5^j = exp(-2*pi*i*j/5)
__constant__ float2 W5c[5] = {
    { 1.0f,                    0.0f                   },
    { 0.30901699437494742f,   -0.95105651629515357f   },
    {-0.80901699437494742f,   -0.58778525229247314f   },
    {-0.80901699437494745f,    0.58778525229247312f   },
    { 0.30901699437494740f,    0.95105651629515364f   }
};

#define SQRT1_2 0.70710678118654752440f

// ---------------- 8-point DFT / unnormalized inverse DFT in registers -------
__device__ __forceinline__ void dft8(float2 x[8]) {
    float2 e0 = x[0], e1 = x[2], e2 = x[4], e3 = x[6];
    float2 o0 = x[1], o1 = x[3], o2 = x[5], o3 = x[7];
    // DFT4 of evens
    float2 b0 = cadd(e0, e2), b1 = csub(e0, e2);
    float2 b2 = cadd(e1, e3), b3 = mul_negi(csub(e1, e3));
    float2 E0 = cadd(b0, b2), E1 = cadd(b1, b3);
    float2 E2 = csub(b0, b2), E3 = csub(b1, b3);
    // DFT4 of odds
    float2 c0 = cadd(o0, o2), c1 = csub(o0, o2);
    float2 c2 = cadd(o1, o3), c3 = mul_negi(csub(o1, o3));
    float2 O0 = cadd(c0, c2), O1 = cadd(c1, c3);
    float2 O2 = csub(c0, c2), O3 = csub(c1, c3);
    // twiddle odds by W8^p
    O1 = cmul(O1, make_float2( SQRT1_2, -SQRT1_2));
    O2 = mul_negi(O2);
    O3 = cmul(O3, make_float2(-SQRT1_2, -SQRT1_2));
    x[0] = cadd(E0, O0); x[4] = csub(E0, O0);
    x[1] = cadd(E1, O1); x[5] = csub(E1, O1);
    x[2] = cadd(E2, O2); x[6] = csub(E2, O2);
    x[3] = cadd(E3, O3); x[7] = csub(E3, O3);
}

__device__ __forceinline__ void idft8(float2 x[8]) {
    float2 e0 = x[0], e1 = x[2], e2 = x[4], e3 = x[6];
    float2 o0 = x[1], o1 = x[3], o2 = x[5], o3 = x[7];
    float2 b0 = cadd(e0, e2), b1 = csub(e0, e2);
    float2 b2 = cadd(e1, e3), b3 = mul_posi(csub(e1, e3));
    float2 E0 = cadd(b0, b2), E1 = cadd(b1, b3);
    float2 E2 = csub(b0, b2), E3 = csub(b1, b3);
    float2 c0 = cadd(o0, o2), c1 = csub(o0, o2);
    float2 c2 = cadd(o1, o3), c3 = mul_posi(csub(o1, o3));
    float2 O0 = cadd(c0, c2), O1 = cadd(c1, c3);
    float2 O2 = csub(c0, c2), O3 = csub(c1, c3);
    O1 = cmul(O1, make_float2( SQRT1_2,  SQRT1_2));
    O2 = mul_posi(O2);
    O3 = cmul(O3, make_float2(-SQRT1_2,  SQRT1_2));
    x[0] = cadd(E0, O0); x[4] = csub(E0, O0);
    x[1] = cadd(E1, O1); x[5] = csub(E1, O1);
    x[2] = cadd(E2, O2); x[6] = csub(E2, O2);
    x[3] = cadd(E3, O3); x[7] = csub(E3, O3);
}

// ---------------- FFT stages (DIF forward / mirrored DIT inverse) ----------
// Forward stage: X_p = (sum_q x_q W_r^{pq}) * W_N^{p*t*STRIDE}, stored at p*h.
// Inverse stage: y'_p = y_p * conj(W_N^{p*t*STRIDE}); x_q = sum_p y'_p W_r^{-pq}.

template<int NS, int STRIDE>
__device__ __forceinline__ void stage8_fwd(float2* sm) {
    const int h = NS / 8;
    for (int u = threadIdx.x; u < N_FFT / 8; u += NTH) {
        int blk = u / h, t = u - blk * h;
        float2* b = sm + blk * NS + t;
        float2 x[8];
#pragma unroll
        for (int q = 0; q < 8; q++) x[q] = b[q * h];
        dft8(x);
        float2 t1 = g_tw[t * STRIDE];
        float2 t2 = cmul(t1, t1);
        float2 t3 = cmul(t2, t1);
        float2 t4 = cmul(t2, t2);
        float2 t5 = cmul(t3, t2);
        float2 t6 = cmul(t3, t3);
        float2 t7 = cmul(t4, t3);
        b[0]     = x[0];
        b[h]     = cmul(x[1], t1);
        b[2 * h] = cmul(x[2], t2);
        b[3 * h] = cmul(x[3], t3);
        b[4 * h] = cmul(x[4], t4);
        b[5 * h] = cmul(x[5], t5);
        b[6 * h] = cmul(x[6], t6);
        b[7 * h] = cmul(x[7], t7);
    }
    __syncthreads();
}

template<int NS, int STRIDE>
__device__ __forceinline__ void stage8_inv(float2* sm) {
    const int h = NS / 8;
    for (int u = threadIdx.x; u < N_FFT / 8; u += NTH) {
        int blk = u / h, t = u - blk * h;
        float2* b = sm + blk * NS + t;
        float2 t1 = g_tw[t * STRIDE];
        float2 t2 = cmul(t1, t1);
        float2 t3 = cmul(t2, t1);
        float2 t4 = cmul(t2, t2);
        float2 t5 = cmul(t3, t2);
        float2 t6 = cmul(t3, t3);
        float2 t7 = cmul(t4, t3);
        float2 y[8];
        y[0] = b[0];
        y[1] = cmulc(b[h],     t1);
        y[2] = cmulc(b[2 * h], t2);
        y[3] = cmulc(b[3 * h], t3);
        y[4] = cmulc(b[4 * h], t4);
        y[5] = cmulc(b[5 * h], t5);
        y[6] = cmulc(b[6 * h], t6);
        y[7] = cmulc(b[7 * h], t7);
        idft8(y);
#pragma unroll
        for (int q = 0; q < 8; q++) b[q * h] = y[q];
    }
    __syncthreads();
}

template<int NS, int STRIDE>
__device__ __forceinline__ void stage2_fwd(float2* sm) {
    const int h = NS / 2;
    for (int u = threadIdx.x; u < N_FFT / 2; u += NTH) {
        int blk = u / h, t = u - blk * h;
        int i = blk * NS + t;
        float2 a = sm[i], b = sm[i + h];
        float2 tw = g_tw[t * STRIDE];
        sm[i]     = cadd(a, b);
        sm[i + h] = cmul(csub(a, b), tw);
    }
    __syncthreads();
}

template<int NS, int STRIDE>
__device__ __forceinline__ void stage2_inv(float2* sm) {
    const int h = NS / 2;
    for (int u = threadIdx.x; u < N_FFT / 2; u += NTH) {
        int blk = u / h, t = u - blk * h;
        int i = blk * NS + t;
        float2 a = sm[i];
        float2 b = cmulc(sm[i + h], g_tw[t * STRIDE]);
        sm[i]     = cadd(a, b);
        sm[i + h] = csub(a, b);
    }
    __syncthreads();
}

template<int NS, int STRIDE>
__device__ __forceinline__ void stage5_fwd(float2* sm) {
    const int h = NS / 5;
    for (int u = threadIdx.x; u < N_FFT / 5; u += NTH) {
        int blk = u / h, t = u - blk * h;
        int base = blk * NS + t;
        float2 x[5];
#pragma unroll
        for (int q = 0; q < 5; q++) x[q] = sm[base + q * h];
        float2 t1 = g_tw[t * STRIDE];
        float2 t2 = cmul(t1, t1);
        float2 t3 = cmul(t2, t1);
        float2 t4 = cmul(t2, t2);
        float2 twp[5];
        twp[1] = t1; twp[2] = t2; twp[3] = t3; twp[4] = t4;
#pragma unroll
        for (int p = 0; p < 5; p++) {
            float2 acc = x[0];
#pragma unroll
            for (int q = 1; q < 5; q++)
                acc = cadd(acc, cmul(x[q], W5c[(p * q) % 5]));
            if (p > 0) acc = cmul(acc, twp[p]);
            sm[base + p * h] = acc;
        }
    }
    __syncthreads();
}

template<int NS, int STRIDE>
__device__ __forceinline__ void stage5_inv(float2* sm) {
    const int h = NS / 5;
    for (int u = threadIdx.x; u < N_FFT / 5; u += NTH) {
        int blk = u / h, t = u - blk * h;
        int base = blk * NS + t;
        float2 t1 = g_tw[t * STRIDE];
        float2 t2 = cmul(t1, t1);
        float2 t3 = cmul(t2, t1);
        float2 t4 = cmul(t2, t2);
        float2 y[5];
        y[0] = sm[base];
        y[1] = cmulc(sm[base + h],     t1);
        y[2] = cmulc(sm[base + 2 * h], t2);
        y[3] = cmulc(sm[base + 3 * h], t3);
        y[4] = cmulc(sm[base + 4 * h], t4);
#pragma unroll
        for (int q = 0; q < 5; q++) {
            float2 acc = y[0];
#pragma unroll
            for (int p = 1; p < 5; p++)
                acc = cadd(acc, cmulc(y[p], W5c[(p * q) % 5]));
            sm[base + q * h] = acc;
        }
    }
    __syncthreads();
}

__device__ __forceinline__ void fft_fwd(float2* sm) {
    stage8_fwd<16000, 1>(sm);
    stage8_fwd<2000,  8>(sm);
    stage2_fwd<250,  64>(sm);
    stage5_fwd<125, 128>(sm);
    stage5_fwd<25,  640>(sm);
    stage5_fwd<5,  3200>(sm);
}

__device__ __forceinline__ void fft_inv(float2* sm) {
    stage5_inv<5,  3200>(sm);
    stage5_inv<25,  640>(sm);
    stage5_inv<125, 128>(sm);
    stage2_inv<250,  64>(sm);
    stage8_inv<2000,  8>(sm);
    stage8_inv<16000, 1>(sm);
}

// ---------------- setup: twiddles + digit-reversal permutation -------------
__global__ void k_setup() {
    int j = blockIdx.x * blockDim.x + threadIdx.x;
    if (j >= N_FFT) return;
    double a = -2.0 * 3.14159265358979323846 * (double)j / (double)N_FFT;
    double sn, cs;
    sincos(a, &sn, &cs);
    g_tw[j] = make_float2((float)cs, (float)sn);

    // sigma: scrambled position -> natural frequency, for stage plan 8,8,2,5,5,5
    const int RADS[6] = {8, 8, 2, 5, 5, 5};
    int p[6];
    int jj = j, len = N_FFT;
    for (int s = 0; s < 6; s++) {
        int h = len / RADS[s];
        p[s] = jj / h;
        jj -= p[s] * h;
        len = h;
    }
    int f = 0;
    for (int s = 5; s >= 0; s--) f = p[s] + RADS[s] * f;
    g_sig[j] = f;
    g_isig[f] = j;
}

// One block per sketch row: find the single +-1 nonzero; early-exit per chunk.
__global__ void k_extract(const float* __restrict__ sk1,
                          const float* __restrict__ sk2) {
    int r = blockIdx.x;
    const float* row = (r < IN_DIM) ? (sk1 + (size_t)r * N_FFT)
                                    : (sk2 + (size_t)(r - IN_DIM) * N_FFT);
    const float4* row4 = (const float4*)row;
    __shared__ int found;
    if (threadIdx.x == 0) found = 0;
    __syncthreads();
    for (int base = 0; base < N_FFT / 4; base += blockDim.x) {
        int j = base + threadIdx.x;
        if (j < N_FFT / 4) {
            float4 v = row4[j];
            if (v.x != 0.f || v.y != 0.f || v.z != 0.f || v.w != 0.f) {
                int   c   = (v.x != 0.f) ? 0 : (v.y != 0.f) ? 1 : (v.z != 0.f) ? 2 : 3;
                float val = (c == 0) ? v.x : (c == 1) ? v.y : (c == 2) ? v.z : v.w;
                g_h[r] = 4 * j + c;
                g_s[r] = val;
                found = 1;
            }
        }
        __syncthreads();
        if (found) break;
    }
}

// ---------------- fused main kernel ----------------
// z = p1 + i*p2 ; one forward FFT ; Hermitian split+multiply in scrambled
// order ; mirrored inverse (natural order, x N) ; signed sqrt.
__global__ void __launch_bounds__(NTH, 1)
k_main(const float* __restrict__ x1, const float* __restrict__ x2,
       float* __restrict__ out) {
    extern __shared__ float2 sm[];
    int b = blockIdx.x;

    // zero
    float4* sm4 = (float4*)sm;
    for (int i = threadIdx.x; i < N_FFT / 2; i += NTH)
        sm4[i] = make_float4(0.f, 0.f, 0.f, 0.f);
    __syncthreads();

    // count-sketch scatter: p1 -> real, p2 -> imag
    const float* r1 = x1 + (size_t)b * IN_DIM;
    const float* r2 = x2 + (size_t)b * IN_DIM;
    for (int k = threadIdx.x; k < IN_DIM; k += NTH) {
        atomicAdd(&sm[g_h[k]].x,          g_s[k]          * r1[k]);
        atomicAdd(&sm[g_h[IN_DIM + k]].y, g_s[IN_DIM + k] * r2[k]);
    }
    __syncthreads();

    fft_fwd(sm);

    // Hermitian separation + pointwise product, in scrambled order.
    // Position j holds Z(sigma(j)). Owner thread (k <= N/2) reads pair,
    // writes G(k) and conj(G(k)). Disjoint position ownership -> race-free.
    for (int j = threadIdx.x; j < N_FFT; j += NTH) {
        int k = g_sig[j];
        if (k > N_FFT / 2) continue;
        if (k == 0 || k == N_FFT / 2) {
            float2 Z = sm[j];                    // F1, F2 both real here
            sm[j] = make_float2(Z.x * Z.y, 0.f);
        } else {
            int jm = g_isig[N_FFT - k];
            float2 Zk = sm[j], Zm = sm[jm];
            float2 F1 = make_float2(0.5f * (Zk.x + Zm.x), 0.5f * (Zk.y - Zm.y));
            float2 F2 = make_float2(0.5f * (Zk.y + Zm.y), -0.5f * (Zk.x - Zm.x));
            float2 G = cmul(F1, F2);
            sm[j]  = G;
            sm[jm] = make_float2(G.x, -G.y);
        }
    }
    __syncthreads();

    fft_inv(sm);   // natural order, unnormalized inverse (x N built in)

    float* dst = out + (size_t)b * N_FFT;
    for (int j = threadIdx.x; j < N_FFT; j += NTH) {
        float c = sm[j].x;
        dst[j] = copysignf(sqrtf(fabsf(c)), c);  // signed sqrt
    }
}

__global__ void k_colnorm(const float* __restrict__ ss) {
    int d = blockIdx.x * blockDim.x + threadIdx.x;
    if (d < N_FFT) {
        float acc = 0.f;
#pragma unroll 8
        for (int b = 0; b < BATCH; b++) {
            float v = ss[(size_t)b * N_FFT + d];
            acc += v * v;
        }
        g_norm[d] = acc;
    }
}

__global__ void k_normalize(float* __restrict__ out) {
    int i = blockIdx.x * blockDim.x + threadIdx.x;
    if (i < BATCH * N_FFT) {
        int d = i % N_FFT;
        float n = sqrtf(g_norm[d]);
        out[i] = out[i] / fmaxf(n, 1e-12f);
    }
}

// ---------------- launch ----------------
extern "C" void kernel_launch(void* const* d_in, const int* in_sizes, int n_in,
                              void* d_out, int out_size) {
    const float* x1  = (const float*)d_in[0];
    const float* x2  = (const float*)d_in[1];
    const float* sk1 = (const float*)d_in[2];
    const float* sk2 = (const float*)d_in[3];
    float* out = (float*)d_out;

    const int smem = N_FFT * sizeof(float2);  // 128000 B
    cudaFuncSetAttribute(k_main, cudaFuncAttributeMaxDynamicSharedMemorySize, smem);

    k_setup<<<(N_FFT + 255) / 256, 256>>>();
    k_extract<<<2 * IN_DIM, 256>>>(sk1, sk2);
    k_main<<<BATCH, NTH, smem>>>(x1, x2, out);
    k_colnorm<<<(N_FFT + 255) / 256, 256>>>(out);
    k_normalize<<<(BATCH * N_FFT + 255) / 256, 256>>>(out);
}

// round 5
// speedup vs baseline: 2.7881x; 1.4177x over previous
#include <cuda_runtime.h>
#include <cuda_bf16.h>
#include <math.h>

#define N_FFT 16000
#define BATCH 512
#define IN_DIM 2048
#define NTH 512

// ---------------- scratch (static __device__, no allocation) ----------------
__device__ int    g_h[2 * IN_DIM];
__device__ float  g_s[2 * IN_DIM];
__device__ float2 g_tw[N_FFT];      // W_N^j = exp(-2*pi*i*j/N)
__device__ int    g_sig[N_FFT];     // scrambled position -> natural frequency
__device__ int    g_isig[N_FFT];    // natural frequency -> scrambled position
__device__ __align__(16) float g_norm[N_FFT];  // per-column sum of squares

// ---------------- complex helpers ----------------
__device__ __forceinline__ float2 cmul(float2 a, float2 b) {
    return make_float2(a.x * b.x - a.y * b.y, a.x * b.y + a.y * b.x);
}
__device__ __forceinline__ float2 cmulc(float2 a, float2 b) {  // a * conj(b)
    return make_float2(a.x * b.x + a.y * b.y, a.y * b.x - a.x * b.y);
}
__device__ __forceinline__ float2 cadd(float2 a, float2 b) {
    return make_float2(a.x + b.x, a.y + b.y);
}
__device__ __forceinline__ float2 csub(float2 a, float2 b) {
    return make_float2(a.x - b.x, a.y - b.y);
}
__device__ __forceinline__ float2 mul_negi(float2 a) { return make_float2(a.y, -a.x); }
__device__ __forceinline__ float2 mul_posi(float2 a) { return make_float2(-a.y, a.x); }

// W5^j = exp(-2*pi*i*j/5)
__constant__ float2 W5c[5] = {
    { 1.0f,                  0.0f                 },
    { 0.30901699437494742f, -0.95105651629515357f },
    {-0.80901699437494742f, -0.58778525229247314f },
    {-0.80901699437494745f,  0.58778525229247312f },
    { 0.30901699437494740f,  0.95105651629515364f }
};
// W10^m = exp(-2*pi*i*m/10), m=0..4
__constant__ float2 W10c[5] = {
    { 1.0f,                  0.0f                 },
    { 0.80901699437494742f, -0.58778525229247312f },
    { 0.30901699437494742f, -0.95105651629515357f },
    {-0.30901699437494742f, -0.95105651629515357f },
    {-0.80901699437494742f, -0.58778525229247312f }
};

#define C_S2 0.70710678118654752440f   // sqrt(1/2)
#define C16A 0.92387953251128676f      // cos(pi/8)
#define C16B 0.38268343236508977f      // sin(pi/8)

// ---------------- small DFTs in registers ----------------
// forward DFT4 (uses -i)
#define DFT4F(a,b,c,d,o0,o1,o2,o3) do { \
    float2 _t0 = cadd(a,c), _t1 = csub(a,c); \
    float2 _t2 = cadd(b,d), _t3 = mul_negi(csub(b,d)); \
    o0 = cadd(_t0,_t2); o1 = cadd(_t1,_t3); \
    o2 = csub(_t0,_t2); o3 = csub(_t1,_t3); } while(0)
// inverse DFT4 (uses +i)
#define DFT4I(a,b,c,d,o0,o1,o2,o3) do { \
    float2 _t0 = cadd(a,c), _t1 = csub(a,c); \
    float2 _t2 = cadd(b,d), _t3 = mul_posi(csub(b,d)); \
    o0 = cadd(_t0,_t2); o1 = cadd(_t1,_t3); \
    o2 = csub(_t0,_t2); o3 = csub(_t1,_t3); } while(0)

__device__ __forceinline__ void dft16(float2 x[16]) {
    float2 A0[4], A1[4], A2[4], A3[4];
    DFT4F(x[0], x[4], x[8],  x[12], A0[0], A0[1], A0[2], A0[3]);
    DFT4F(x[1], x[5], x[9],  x[13], A1[0], A1[1], A1[2], A1[3]);
    DFT4F(x[2], x[6], x[10], x[14], A2[0], A2[1], A2[2], A2[3]);
    DFT4F(x[3], x[7], x[11], x[15], A3[0], A3[1], A3[2], A3[3]);
    // twiddle A_{n1}[m] by W16^{n1*m}
    A1[1] = cmul(A1[1], make_float2( C16A, -C16B));   // W16^1
    A1[2] = cmul(A1[2], make_float2( C_S2, -C_S2));   // W16^2
    A1[3] = cmul(A1[3], make_float2( C16B, -C16A));   // W16^3
    A2[1] = cmul(A2[1], make_float2( C_S2, -C_S2));   // W16^2
    A2[2] = mul_negi(A2[2]);                          // W16^4
    A2[3] = cmul(A2[3], make_float2(-C_S2, -C_S2));   // W16^6
    A3[1] = cmul(A3[1], make_float2( C16B, -C16A));   // W16^3
    A3[2] = cmul(A3[2], make_float2(-C_S2, -C_S2));   // W16^6
    A3[3] = cmul(A3[3], make_float2(-C16A,  C16B));   // W16^9
#pragma unroll
    for (int m = 0; m < 4; m++)
        DFT4F(A0[m], A1[m], A2[m], A3[m], x[m], x[m+4], x[m+8], x[m+12]);
}

__device__ __forceinline__ void idft16(float2 x[16]) {
    float2 A0[4], A1[4], A2[4], A3[4];
    DFT4I(x[0], x[4], x[8],  x[12], A0[0], A0[1], A0[2], A0[3]);
    DFT4I(x[1], x[5], x[9],  x[13], A1[0], A1[1], A1[2], A1[3]);
    DFT4I(x[2], x[6], x[10], x[14], A2[0], A2[1], A2[2], A2[3]);
    DFT4I(x[3], x[7], x[11], x[15], A3[0], A3[1], A3[2], A3[3]);
    A1[1] = cmul(A1[1], make_float2( C16A,  C16B));
    A1[2] = cmul(A1[2], make_float2( C_S2,  C_S2));
    A1[3] = cmul(A1[3], make_float2( C16B,  C16A));
    A2[1] = cmul(A2[1], make_float2( C_S2,  C_S2));
    A2[2] = mul_posi(A2[2]);
    A2[3] = cmul(A2[3], make_float2(-C_S2,  C_S2));
    A3[1] = cmul(A3[1], make_float2( C16B,  C16A));
    A3[2] = cmul(A3[2], make_float2(-C_S2,  C_S2));
    A3[3] = cmul(A3[3], make_float2(-C16A, -C16B));
#pragma unroll
    for (int m = 0; m < 4; m++)
        DFT4I(A0[m], A1[m], A2[m], A3[m], x[m], x[m+4], x[m+8], x[m+12]);
}

__device__ __forceinline__ void dft5f(float2 a0, float2 a1, float2 a2,
                                      float2 a3, float2 a4, float2 o[5]) {
#pragma unroll
    for (int p = 0; p < 5; p++) {
        float2 acc = a0;
        acc = cadd(acc, cmul(a1, W5c[p % 5]));
        acc = cadd(acc, cmul(a2, W5c[(2*p) % 5]));
        acc = cadd(acc, cmul(a3, W5c[(3*p) % 5]));
        acc = cadd(acc, cmul(a4, W5c[(4*p) % 5]));
        o[p] = acc;
    }
}
__device__ __forceinline__ void dft5i(float2 a0, float2 a1, float2 a2,
                                      float2 a3, float2 a4, float2 o[5]) {
#pragma unroll
    for (int p = 0; p < 5; p++) {
        float2 acc = a0;
        acc = cadd(acc, cmulc(a1, W5c[p % 5]));
        acc = cadd(acc, cmulc(a2, W5c[(2*p) % 5]));
        acc = cadd(acc, cmulc(a3, W5c[(3*p) % 5]));
        acc = cadd(acc, cmulc(a4, W5c[(4*p) % 5]));
        o[p] = acc;
    }
}

__device__ __forceinline__ void dft10(float2 x[10]) {
    float2 B0[5], B1[5];
    dft5f(x[0], x[2], x[4], x[6], x[8], B0);
    dft5f(x[1], x[3], x[5], x[7], x[9], B1);
#pragma unroll
    for (int m = 0; m < 5; m++) {
        float2 t = cmul(B1[m], W10c[m]);
        x[m]     = cadd(B0[m], t);
        x[m + 5] = csub(B0[m], t);
    }
}
__device__ __forceinline__ void idft10(float2 x[10]) {
    float2 B0[5], B1[5];
    dft5i(x[0], x[2], x[4], x[6], x[8], B0);
    dft5i(x[1], x[3], x[5], x[7], x[9], B1);
#pragma unroll
    for (int m = 0; m < 5; m++) {
        float2 t = cmulc(B1[m], W10c[m]);
        x[m]     = cadd(B0[m], t);
        x[m + 5] = csub(B0[m], t);
    }
}

// ---------------- twiddle power chains ----------------
__device__ __forceinline__ void twchain16(float2 t1, float2 tw[16]) {
    tw[1] = t1;
    tw[2]  = cmul(t1, t1);
    tw[3]  = cmul(tw[2], t1);
    tw[4]  = cmul(tw[2], tw[2]);
    tw[5]  = cmul(tw[3], tw[2]);
    tw[6]  = cmul(tw[3], tw[3]);
    tw[7]  = cmul(tw[4], tw[3]);
    tw[8]  = cmul(tw[4], tw[4]);
    tw[9]  = cmul(tw[5], tw[4]);
    tw[10] = cmul(tw[5], tw[5]);
    tw[11] = cmul(tw[6], tw[5]);
    tw[12] = cmul(tw[6], tw[6]);
    tw[13] = cmul(tw[7], tw[6]);
    tw[14] = cmul(tw[7], tw[7]);
    tw[15] = cmul(tw[8], tw[7]);
}
__device__ __forceinline__ void twchain10(float2 t1, float2 tw[10]) {
    tw[1] = t1;
    tw[2] = cmul(t1, t1);
    tw[3] = cmul(tw[2], t1);
    tw[4] = cmul(tw[2], tw[2]);
    tw[5] = cmul(tw[3], tw[2]);
    tw[6] = cmul(tw[3], tw[3]);
    tw[7] = cmul(tw[4], tw[3]);
    tw[8] = cmul(tw[4], tw[4]);
    tw[9] = cmul(tw[5], tw[4]);
}

// ---------------- FFT stages ----------------
template<int STRIDE>
__device__ __forceinline__ void stage16_fwd(float2* sm) {
    const int NS = 16000, h = NS / 16;       // first stage: blk == 0
    for (int t = threadIdx.x; t < h; t += NTH) {
        float2* b = sm + t;
        float2 x[16];
#pragma unroll
        for (int q = 0; q < 16; q++) x[q] = b[q * h];
        dft16(x);
        float2 tw[16];
        twchain16(g_tw[t * STRIDE], tw);
        b[0] = x[0];
#pragma unroll
        for (int p = 1; p < 16; p++) b[p * h] = cmul(x[p], tw[p]);
    }
    __syncthreads();
}

template<int STRIDE>
__device__ __forceinline__ void stage16_inv(float2* sm) {
    const int NS = 16000, h = NS / 16;
    for (int t = threadIdx.x; t < h; t += NTH) {
        float2* b = sm + t;
        float2 tw[16];
        twchain16(g_tw[t * STRIDE], tw);
        float2 y[16];
        y[0] = b[0];
#pragma unroll
        for (int p = 1; p < 16; p++) y[p] = cmulc(b[p * h], tw[p]);
        idft16(y);
#pragma unroll
        for (int q = 0; q < 16; q++) b[q * h] = y[q];
    }
    __syncthreads();
}

template<int NS, int STRIDE>
__device__ __forceinline__ void stage10_fwd(float2* sm) {
    const int h = NS / 10;
    for (int u = threadIdx.x; u < N_FFT / 10; u += NTH) {
        int blk = u / h, t = u - blk * h;
        float2* b = sm + blk * NS + t;
        float2 x[10];
#pragma unroll
        for (int q = 0; q < 10; q++) x[q] = b[q * h];
        dft10(x);
        if (NS != 10) {                       // last stage: t==0, no twiddles
            float2 tw[10];
            twchain10(g_tw[t * STRIDE], tw);
#pragma unroll
            for (int p = 1; p < 10; p++) x[p] = cmul(x[p], tw[p]);
        }
#pragma unroll
        for (int p = 0; p < 10; p++) b[p * h] = x[p];
    }
    __syncthreads();
}

template<int NS, int STRIDE>
__device__ __forceinline__ void stage10_inv(float2* sm) {
    const int h = NS / 10;
    for (int u = threadIdx.x; u < N_FFT / 10; u += NTH) {
        int blk = u / h, t = u - blk * h;
        float2* b = sm + blk * NS + t;
        float2 y[10];
#pragma unroll
        for (int p = 0; p < 10; p++) y[p] = b[p * h];
        if (NS != 10) {
            float2 tw[10];
            twchain10(g_tw[t * STRIDE], tw);
#pragma unroll
            for (int p = 1; p < 10; p++) y[p] = cmulc(y[p], tw[p]);
        }
        idft10(y);
#pragma unroll
        for (int q = 0; q < 10; q++) b[q * h] = y[q];
    }
    __syncthreads();
}

__device__ __forceinline__ void fft_fwd(float2* sm) {
    stage16_fwd<1>(sm);                 // 16000 -> 1000
    stage10_fwd<1000, 16>(sm);          // 1000  -> 100
    stage10_fwd<100, 160>(sm);          // 100   -> 10
    stage10_fwd<10, 1600>(sm);          // 10    -> 1 (no twiddles)
}
__device__ __forceinline__ void fft_inv(float2* sm) {
    stage10_inv<10, 1600>(sm);
    stage10_inv<100, 160>(sm);
    stage10_inv<1000, 16>(sm);
    stage16_inv<1>(sm);
}

// ---------------- setup: twiddles + digit-reversal + norm clear -------------
__global__ void k_setup() {
    int j = blockIdx.x * blockDim.x + threadIdx.x;
    if (j >= N_FFT) return;
    double a = -2.0 * 3.14159265358979323846 * (double)j / (double)N_FFT;
    double sn, cs;
    sincos(a, &sn, &cs);
    g_tw[j] = make_float2((float)cs, (float)sn);
    g_norm[j] = 0.f;

    // sigma for stage plan {16,10,10,10}
    const int RADS[4] = {16, 10, 10, 10};
    int p[4];
    int jj = j, len = N_FFT;
    for (int s = 0; s < 4; s++) {
        int h = len / RADS[s];
        p[s] = jj / h;
        jj -= p[s] * h;
        len = h;
    }
    int f = 0;
    for (int s = 3; s >= 0; s--) f = p[s] + RADS[s] * f;
    g_sig[j] = f;
    g_isig[f] = j;
}

// One block per sketch row: find the single +-1 nonzero; early-exit per chunk.
__global__ void k_extract(const float* __restrict__ sk1,
                          const float* __restrict__ sk2) {
    int r = blockIdx.x;
    const float* row = (r < IN_DIM) ? (sk1 + (size_t)r * N_FFT)
                                    : (sk2 + (size_t)(r - IN_DIM) * N_FFT);
    const float4* row4 = (const float4*)row;
    __shared__ int found;
    if (threadIdx.x == 0) found = 0;
    __syncthreads();
    for (int base = 0; base < N_FFT / 4; base += blockDim.x) {
        int j = base + threadIdx.x;
        if (j < N_FFT / 4) {
            float4 v = row4[j];
            if (v.x != 0.f || v.y != 0.f || v.z != 0.f || v.w != 0.f) {
                int   c   = (v.x != 0.f) ? 0 : (v.y != 0.f) ? 1 : (v.z != 0.f) ? 2 : 3;
                float val = (c == 0) ? v.x : (c == 1) ? v.y : (c == 2) ? v.z : v.w;
                g_h[r] = 4 * j + c;
                g_s[r] = val;
                found = 1;
            }
        }
        __syncthreads();
        if (found) break;
    }
}

// ---------------- fused main kernel ----------------
__global__ void __launch_bounds__(NTH, 1)
k_main(const float* __restrict__ x1, const float* __restrict__ x2,
       float* __restrict__ out) {
    extern __shared__ float2 sm[];
    int b = blockIdx.x;

    float4* sm4 = (float4*)sm;
    for (int i = threadIdx.x; i < N_FFT / 2; i += NTH)
        sm4[i] = make_float4(0.f, 0.f, 0.f, 0.f);
    __syncthreads();

    // count-sketch scatter: p1 -> real, p2 -> imag
    const float* r1 = x1 + (size_t)b * IN_DIM;
    const float* r2 = x2 + (size_t)b * IN_DIM;
    for (int k = threadIdx.x; k < IN_DIM; k += NTH) {
        atomicAdd(&sm[g_h[k]].x,          g_s[k]          * r1[k]);
        atomicAdd(&sm[g_h[IN_DIM + k]].y, g_s[IN_DIM + k] * r2[k]);
    }
    __syncthreads();

    fft_fwd(sm);

    // Hermitian separation + pointwise product in scrambled order.
    for (int j = threadIdx.x; j < N_FFT; j += NTH) {
        int k = g_sig[j];
        if (k > N_FFT / 2) continue;
        if (k == 0 || k == N_FFT / 2) {
            float2 Z = sm[j];
            sm[j] = make_float2(Z.x * Z.y, 0.f);
        } else {
            int jm = g_isig[N_FFT - k];
            float2 Zk = sm[j], Zm = sm[jm];
            float2 F1 = make_float2(0.5f * (Zk.x + Zm.x), 0.5f * (Zk.y - Zm.y));
            float2 F2 = make_float2(0.5f * (Zk.y + Zm.y), -0.5f * (Zk.x - Zm.x));
            float2 G = cmul(F1, F2);
            sm[j]  = G;
            sm[jm] = make_float2(G.x, -G.y);
        }
    }
    __syncthreads();

    fft_inv(sm);   // natural order, unnormalized inverse (x N built in)

    float* dst = out + (size_t)b * N_FFT;
    for (int j = threadIdx.x; j < N_FFT; j += NTH) {
        float c = sm[j].x;
        dst[j] = copysignf(sqrtf(fabsf(c)), c);  // signed sqrt
    }
}

// grid (32, 16): 512 CTAs, block 128; each thread: one float4 column over a
// 32-row batch chunk, atomicAdd partials into g_norm.
__global__ void k_colnorm(const float* __restrict__ ss) {
    int c4 = blockIdx.x * blockDim.x + threadIdx.x;
    if (c4 >= N_FFT / 4) return;
    int b0 = blockIdx.y * (BATCH / 16);
    const float4* p = (const float4*)ss;
    float4 acc = make_float4(0.f, 0.f, 0.f, 0.f);
#pragma unroll 4
    for (int b = b0; b < b0 + BATCH / 16; b++) {
        float4 v = p[(size_t)b * (N_FFT / 4) + c4];
        acc.x += v.x * v.x; acc.y += v.y * v.y;
        acc.z += v.z * v.z; acc.w += v.w * v.w;
    }
    atomicAdd(&g_norm[4 * c4 + 0], acc.x);
    atomicAdd(&g_norm[4 * c4 + 1], acc.y);
    atomicAdd(&g_norm[4 * c4 + 2], acc.z);
    atomicAdd(&g_norm[4 * c4 + 3], acc.w);
}

__global__ void k_normalize(float* __restrict__ out) {
    int i = blockIdx.x * blockDim.x + threadIdx.x;
    if (i >= BATCH * (N_FFT / 4)) return;
    int c4 = i % (N_FFT / 4);
    float4 nv = ((const float4*)g_norm)[c4];
    float4* o4 = (float4*)out;
    float4 v = o4[i];
    v.x /= fmaxf(sqrtf(nv.x), 1e-12f);
    v.y /= fmaxf(sqrtf(nv.y), 1e-12f);
    v.z /= fmaxf(sqrtf(nv.z), 1e-12f);
    v.w /= fmaxf(sqrtf(nv.w), 1e-12f);
    o4[i] = v;
}

// ---------------- launch ----------------
extern "C" void kernel_launch(void* const* d_in, const int* in_sizes, int n_in,
                              void* d_out, int out_size) {
    const float* x1  = (const float*)d_in[0];
    const float* x2  = (const float*)d_in[1];
    const float* sk1 = (const float*)d_in[2];
    const float* sk2 = (const float*)d_in[3];
    float* out = (float*)d_out;

    const int smem = N_FFT * sizeof(float2);  // 128000 B
    cudaFuncSetAttribute(k_main, cudaFuncAttributeMaxDynamicSharedMemorySize, smem);

    k_setup<<<(N_FFT + 255) / 256, 256>>>();
    k_extract<<<2 * IN_DIM, 256>>>(sk1, sk2);
    k_main<<<BATCH, NTH, smem>>>(x1, x2, out);
    dim3 cn_grid((N_FFT / 4 + 127) / 128, 16);
    k_colnorm<<<cn_grid, 128>>>(out);
    k_normalize<<<(BATCH * N_FFT / 4 + 255) / 256, 256>>>(out);
}